// round 3
// baseline (speedup 1.0000x reference)
#include <cuda_runtime.h>

// Toy force field: f = -grad_p( sum(MLP(p)) ), MLP = 2 -> 8 -> 4 -> 2 with ReLU.
// Analytical backward:
//   v[k]   = W3[0][k] + W3[1][k]                       (dE/dh2)
//   u      = m2 .* v,  m2 = (h2p > 0)
//   w      = m1 .* (W2^T u), m1 = (h1p > 0)
//   f      = -(W1^T w)
// LUT: g[m2] = -(W2^T (m2 .* v))  -- 16 entries x 8 floats, negation baked in.
// Then f = W1^T (m1 .* g[m2]) directly.

#define NTHREADS 256
#define NBLOCKS  2048

__global__ __launch_bounds__(NTHREADS) void toy_force_kernel(
    const float4* __restrict__ pos4,
    const float*  __restrict__ W1g,
    const float*  __restrict__ b1g,
    const float*  __restrict__ W2g,
    const float*  __restrict__ b2g,
    const float*  __restrict__ W3g,
    float4*       __restrict__ out4,
    int npairs)
{
    __shared__ float sW1[16];
    __shared__ float sb1[8];
    __shared__ float sW2[32];
    __shared__ float sb2[4];
    __shared__ float sv[4];
    __shared__ float sg[16 * 10];   // stride 10 -> conflict-free LDS.64 starts

    const int t = threadIdx.x;

    // Stage raw weights into shared (one warp's worth of threads).
    if (t < 16)               sW1[t]      = W1g[t];
    else if (t < 24)          sb1[t - 16] = b1g[t - 16];
    else if (t < 56)          sW2[t - 24] = W2g[t - 24];
    else if (t < 60)          sb2[t - 56] = b2g[t - 56];
    else if (t < 64)          sv[t - 60]  = W3g[t - 60] + W3g[4 + (t - 60)];
    __syncthreads();

    // Build backward LUT: g[idx][j] = -sum_k (bit_k(idx) ? v[k] : 0) * W2[k][j]
    if (t < 16) {
        const float u0 = (t & 1) ? sv[0] : 0.f;
        const float u1 = (t & 2) ? sv[1] : 0.f;
        const float u2 = (t & 4) ? sv[2] : 0.f;
        const float u3 = (t & 8) ? sv[3] : 0.f;
#pragma unroll
        for (int j = 0; j < 8; j++) {
            sg[t * 10 + j] = -(u0 * sW2[0 * 8 + j] + u1 * sW2[1 * 8 + j] +
                               u2 * sW2[2 * 8 + j] + u3 * sW2[3 * 8 + j]);
        }
    }
    __syncthreads();

    // Per-thread register copies of forward weights.
    float W1r0[8], W1r1[8], b1r[8], W2r[4][8], b2r[4];
#pragma unroll
    for (int j = 0; j < 8; j++) {
        W1r0[j] = sW1[2 * j];
        W1r1[j] = sW1[2 * j + 1];
        b1r[j]  = sb1[j];
    }
#pragma unroll
    for (int k = 0; k < 4; k++) {
        b2r[k] = sb2[k];
#pragma unroll
        for (int j = 0; j < 8; j++) W2r[k][j] = sW2[k * 8 + j];
    }

    const int stride = gridDim.x * blockDim.x;
    for (int i = blockIdx.x * blockDim.x + t; i < npairs; i += stride) {
        const float4 p = pos4[i];
        float fxo[2], fyo[2];

#pragma unroll
        for (int s = 0; s < 2; s++) {
            const float x = s ? p.z : p.x;
            const float y = s ? p.w : p.y;

            // Layer 1 forward
            float h1p[8], h1[8];
#pragma unroll
            for (int j = 0; j < 8; j++) {
                h1p[j] = fmaf(x, W1r0[j], fmaf(y, W1r1[j], b1r[j]));
                h1[j]  = fmaxf(h1p[j], 0.f);
            }

            // Layer 2 forward (pre-activation only; mask is all we need)
            float h2p[4];
#pragma unroll
            for (int k = 0; k < 4; k++) {
                float a = b2r[k];
#pragma unroll
                for (int j = 0; j < 8; j++) a = fmaf(h1[j], W2r[k][j], a);
                h2p[k] = a;
            }

            // 4-bit mask index
            const int idx = (int)(h2p[0] > 0.f)
                          | ((int)(h2p[1] > 0.f) << 1)
                          | ((int)(h2p[2] > 0.f) << 2)
                          | ((int)(h2p[3] > 0.f) << 3);

            // Load g = -(W2^T (m2.*v)) from LUT: 4x LDS.64, conflict-free
            const float2* gp = reinterpret_cast<const float2*>(&sg[idx * 10]);
            const float2 g01 = gp[0], g23 = gp[1], g45 = gp[2], g67 = gp[3];
            float g[8];
            g[0] = g01.x; g[1] = g01.y; g[2] = g23.x; g[3] = g23.y;
            g[4] = g45.x; g[5] = g45.y; g[6] = g67.x; g[7] = g67.y;

            // f = W1^T (m1 .* g)   (negation already baked into g)
            float fx = 0.f, fy = 0.f;
#pragma unroll
            for (int j = 0; j < 8; j++) {
                if (h1p[j] > 0.f) {
                    fx = fmaf(g[j], W1r0[j], fx);
                    fy = fmaf(g[j], W1r1[j], fy);
                }
            }
            fxo[s] = fx;
            fyo[s] = fy;
        }

        out4[i] = make_float4(fxo[0], fyo[0], fxo[1], fyo[1]);
    }
}

extern "C" void kernel_launch(void* const* d_in, const int* in_sizes, int n_in,
                              void* d_out, int out_size) {
    const float4* pos4 = (const float4*)d_in[0];
    const float*  W1   = (const float*)d_in[1];
    const float*  b1   = (const float*)d_in[2];
    const float*  W2   = (const float*)d_in[3];
    const float*  b2   = (const float*)d_in[4];
    const float*  W3   = (const float*)d_in[5];
    float4*       out4 = (float4*)d_out;

    const int npairs = in_sizes[0] / 4;   // pos has N*2 floats; 4 floats = 2 samples
    int grid = (npairs + NTHREADS - 1) / NTHREADS;
    if (grid > NBLOCKS) grid = NBLOCKS;

    toy_force_kernel<<<grid, NTHREADS>>>(pos4, W1, b1, W2, b2, W3, out4, npairs);
}

// round 6
// speedup vs baseline: 1.0997x; 1.0997x over previous
#include <cuda_runtime.h>

// Toy force field: f = -grad_p( sum(MLP(p)) ), MLP = 2 -> 8 -> 4 -> 2 with ReLU.
// Analytical backward via 16-entry LUT g[m2] = -(W2^T (m2 .* v)), v = colsum(W3).
// f = W1^T (m1 .* g[m2]).
//
// Round-3 changes:
//  - fma.rn.f32x2 packed fp32 math for layer1 + layer2 (halves fma-pipe slots)
//  - b2 folded into sign threshold (h2p>0  <=>  acc_lo+acc_hi > -b2)
//  - ILP-4: 4 independent LDG.128 batched per thread (MLP 4x for latency hiding)
//  - LUT stride 8 -> 2x LDS.128 per sample instead of 4x LDS.64

#define NTHREADS 256
#define ILP 4

typedef unsigned long long ull;

__device__ __forceinline__ ull pack2(float lo, float hi) {
    ull r;
    asm("mov.b64 %0, {%1, %2};"
        : "=l"(r) : "r"(__float_as_uint(lo)), "r"(__float_as_uint(hi)));
    return r;
}
__device__ __forceinline__ void unpack2(ull v, float& lo, float& hi) {
    unsigned a, b;
    asm("mov.b64 {%0, %1}, %2;" : "=r"(a), "=r"(b) : "l"(v));
    lo = __uint_as_float(a);
    hi = __uint_as_float(b);
}
__device__ __forceinline__ ull ffma2(ull a, ull b, ull c) {
    ull d;
    asm("fma.rn.f32x2 %0, %1, %2, %3;" : "=l"(d) : "l"(a), "l"(b), "l"(c));
    return d;
}
__device__ __forceinline__ ull fmul2(ull a, ull b) {
    ull d;
    asm("mul.rn.f32x2 %0, %1, %2;" : "=l"(d) : "l"(a), "l"(b));
    return d;
}

__global__ __launch_bounds__(NTHREADS, 2) void toy_force_kernel(
    const float4* __restrict__ pos4,
    const float*  __restrict__ W1g,
    const float*  __restrict__ b1g,
    const float*  __restrict__ W2g,
    const float*  __restrict__ b2g,
    const float*  __restrict__ W3g,
    float4*       __restrict__ out4,
    int npairs)
{
    __shared__ float sW1[16];
    __shared__ float sb1[8];
    __shared__ float sW2[32];
    __shared__ float sb2[4];
    __shared__ float sv[4];
    __shared__ __align__(16) float sg[16 * 8];   // stride 8 -> 16B-aligned LDS.128

    const int t = threadIdx.x;

    // Stage raw weights into shared.
    if (t < 16)               sW1[t]      = W1g[t];
    else if (t < 24)          sb1[t - 16] = b1g[t - 16];
    else if (t < 56)          sW2[t - 24] = W2g[t - 24];
    else if (t < 60)          sb2[t - 56] = b2g[t - 56];
    else if (t < 64)          sv[t - 60]  = W3g[t - 60] + W3g[4 + (t - 60)];
    __syncthreads();

    // Backward LUT: g[idx][j] = -sum_k (bit_k(idx) ? v[k] : 0) * W2[k][j]
    if (t < 16) {
        const float u0 = (t & 1) ? sv[0] : 0.f;
        const float u1 = (t & 2) ? sv[1] : 0.f;
        const float u2 = (t & 4) ? sv[2] : 0.f;
        const float u3 = (t & 8) ? sv[3] : 0.f;
#pragma unroll
        for (int j = 0; j < 8; j++) {
            sg[t * 8 + j] = -(u0 * sW2[0 * 8 + j] + u1 * sW2[1 * 8 + j] +
                              u2 * sW2[2 * 8 + j] + u3 * sW2[3 * 8 + j]);
        }
    }
    __syncthreads();

    // Packed per-thread weights.
    ull W10_2[4], W11_2[4], b1_2[4], W2_2[4][4];
    float w10[8], w11[8], nb2[4];
#pragma unroll
    for (int jj = 0; jj < 4; jj++) {
        W10_2[jj] = pack2(sW1[4 * jj],     sW1[4 * jj + 2]);  // W1[2jj][0], W1[2jj+1][0]
        W11_2[jj] = pack2(sW1[4 * jj + 1], sW1[4 * jj + 3]);  // W1[2jj][1], W1[2jj+1][1]
        b1_2[jj]  = pack2(sb1[2 * jj],     sb1[2 * jj + 1]);
    }
#pragma unroll
    for (int j = 0; j < 8; j++) { w10[j] = sW1[2 * j]; w11[j] = sW1[2 * j + 1]; }
#pragma unroll
    for (int k = 0; k < 4; k++) {
        nb2[k] = -sb2[k];
#pragma unroll
        for (int jj = 0; jj < 4; jj++)
            W2_2[k][jj] = pack2(sW2[8 * k + 2 * jj], sW2[8 * k + 2 * jj + 1]);
    }

    const int TOT = gridDim.x * blockDim.x;
    const int i0  = blockIdx.x * blockDim.x + t;

    // Batched independent loads (MLP = ILP).
    float4 p[ILP];
    bool ok[ILP];
#pragma unroll
    for (int u = 0; u < ILP; u++) {
        const int i = i0 + u * TOT;
        ok[u] = (i < npairs);
        if (ok[u]) p[u] = pos4[i];
    }

#pragma unroll
    for (int u = 0; u < ILP; u++) {
        if (!ok[u]) continue;
        float fo[4];
#pragma unroll
        for (int s = 0; s < 2; s++) {
            const float x = s ? p[u].z : p[u].x;
            const float y = s ? p[u].w : p[u].y;
            const ull xx = pack2(x, x);
            const ull yy = pack2(y, y);

            // Layer 1 (packed over neuron pairs)
            float h1p[8], h1[8];
            ull h1_2[4];
#pragma unroll
            for (int jj = 0; jj < 4; jj++) {
                ull h = ffma2(xx, W10_2[jj], ffma2(yy, W11_2[jj], b1_2[jj]));
                unpack2(h, h1p[2 * jj], h1p[2 * jj + 1]);
                h1[2 * jj]     = fmaxf(h1p[2 * jj], 0.f);
                h1[2 * jj + 1] = fmaxf(h1p[2 * jj + 1], 0.f);
                h1_2[jj] = pack2(h1[2 * jj], h1[2 * jj + 1]);
            }

            // Layer 2: only signs needed; bias folded into threshold.
            int idx = 0;
#pragma unroll
            for (int k = 0; k < 4; k++) {
                ull acc = fmul2(h1_2[0], W2_2[k][0]);
                acc = ffma2(h1_2[1], W2_2[k][1], acc);
                acc = ffma2(h1_2[2], W2_2[k][2], acc);
                acc = ffma2(h1_2[3], W2_2[k][3], acc);
                float lo, hi;
                unpack2(acc, lo, hi);
                idx |= (int)((lo + hi) > nb2[k]) << k;
            }

            // g = -(W2^T (m2 .* v)) via LUT: 2x LDS.128
            const float4* gp = reinterpret_cast<const float4*>(&sg[idx * 8]);
            const float4 ga = gp[0];
            const float4 gb = gp[1];
            const float g[8] = {ga.x, ga.y, ga.z, ga.w, gb.x, gb.y, gb.z, gb.w};

            // f = W1^T (m1 .* g)
            float fx = 0.f, fy = 0.f;
#pragma unroll
            for (int j = 0; j < 8; j++) {
                if (h1p[j] > 0.f) {
                    fx = fmaf(g[j], w10[j], fx);
                    fy = fmaf(g[j], w11[j], fy);
                }
            }
            fo[2 * s]     = fx;
            fo[2 * s + 1] = fy;
        }
        out4[i0 + u * TOT] = make_float4(fo[0], fo[1], fo[2], fo[3]);
    }
}

extern "C" void kernel_launch(void* const* d_in, const int* in_sizes, int n_in,
                              void* d_out, int out_size) {
    const float4* pos4 = (const float4*)d_in[0];
    const float*  W1   = (const float*)d_in[1];
    const float*  b1   = (const float*)d_in[2];
    const float*  W2   = (const float*)d_in[3];
    const float*  b2   = (const float*)d_in[4];
    const float*  W3   = (const float*)d_in[5];
    float4*       out4 = (float4*)d_out;

    const int npairs = in_sizes[0] / 4;   // floats -> float4 count (2 samples each)
    int grid = (npairs + NTHREADS * ILP - 1) / (NTHREADS * ILP);
    if (grid < 1) grid = 1;

    toy_force_kernel<<<grid, NTHREADS>>>(pos4, W1, b1, W2, b2, W3, out4, npairs);
}